// round 2
// baseline (speedup 1.0000x reference)
#include <cuda_runtime.h>
#include <cstdint>

#define Bb 4
#define Nn 10000
#define Ee 160000
#define Mm 4
#define Hh 64
#define OUTd 64
#define Ff 64

#define ROWS (Bb*Nn*Mm)      /* 160000 projected rows, each 128 -> 64 */
#define EDGES (Bb*Ee)        /* 640000 */

// Scratch (allocation-free rule: __device__ globals)
__device__ float g_nh[(size_t)ROWS * OUTd];   // 40.96 MB projected features
__device__ float g_coeff[EDGES];              // 2.56 MB per-edge gate

// ---------------------------------------------------------------------------
// Kernel 1: projection  nh_fts[row, o] = sum_c x[row,c] * W[c,o] + b[o]
//   x[row, 0:64]  = node_fts[row, :]
//   x[row, 64:128]= hidden[row, :]
// 64 rows per block, 256 threads, thread tile = 4 rows x 4 outs.
// Shared: Ws[128][64] (32KB) + Xs[64][132] (33.8KB)  -> 66560 B dynamic smem
// ---------------------------------------------------------------------------
#define PROJ_ROWS_PER_BLK 64
#define XPITCH 132
#define PROJ_SMEM_BYTES ((128*64 + PROJ_ROWS_PER_BLK*XPITCH) * 4)

__global__ __launch_bounds__(256, 3)
void k_project(const float* __restrict__ node,
               const float* __restrict__ hidden,
               const float* __restrict__ Wnh,
               const float* __restrict__ bnh)
{
    extern __shared__ float sm[];
    float* Ws = sm;                  // [128][64]
    float* Xs = sm + 128 * 64;       // [64][XPITCH]

    const int tid  = threadIdx.x;
    const int row0 = blockIdx.x * PROJ_ROWS_PER_BLK;

    // Load W (8192 floats)
    #pragma unroll
    for (int i = tid; i < 128 * 64; i += 256) Ws[i] = Wnh[i];

    // Load X tile: 64 rows x 128 cols (first 64 = node, last 64 = hidden)
    #pragma unroll
    for (int i = tid; i < PROJ_ROWS_PER_BLK * 128; i += 256) {
        int r = i >> 7;
        int c = i & 127;
        int grow = row0 + r;
        float v = (c < 64) ? node[(size_t)grow * 64 + c]
                           : hidden[(size_t)grow * 64 + (c - 64)];
        Xs[r * XPITCH + c] = v;
    }
    __syncthreads();

    const int obase = (tid & 15) * 4;   // 16 col-groups * 4 = 64 outputs
    const int rbase = (tid >> 4) * 4;   // 16 row-groups * 4 = 64 rows

    float acc[4][4];
    float b0 = __ldg(&bnh[obase + 0]);
    float b1 = __ldg(&bnh[obase + 1]);
    float b2 = __ldg(&bnh[obase + 2]);
    float b3 = __ldg(&bnh[obase + 3]);
    #pragma unroll
    for (int i = 0; i < 4; i++) {
        acc[i][0] = b0; acc[i][1] = b1; acc[i][2] = b2; acc[i][3] = b3;
    }

    #pragma unroll 4
    for (int c = 0; c < 128; c++) {
        const float4 w = *(const float4*)&Ws[c * 64 + obase];
        float x0 = Xs[(rbase + 0) * XPITCH + c];
        float x1 = Xs[(rbase + 1) * XPITCH + c];
        float x2 = Xs[(rbase + 2) * XPITCH + c];
        float x3 = Xs[(rbase + 3) * XPITCH + c];
        acc[0][0] += x0 * w.x; acc[0][1] += x0 * w.y; acc[0][2] += x0 * w.z; acc[0][3] += x0 * w.w;
        acc[1][0] += x1 * w.x; acc[1][1] += x1 * w.y; acc[1][2] += x1 * w.z; acc[1][3] += x1 * w.w;
        acc[2][0] += x2 * w.x; acc[2][1] += x2 * w.y; acc[2][2] += x2 * w.z; acc[2][3] += x2 * w.w;
        acc[3][0] += x3 * w.x; acc[3][1] += x3 * w.y; acc[3][2] += x3 * w.z; acc[3][3] += x3 * w.w;
    }

    #pragma unroll
    for (int i = 0; i < 4; i++) {
        size_t off = (size_t)(row0 + rbase + i) * 64 + obase;
        float4 v = make_float4(acc[i][0], acc[i][1], acc[i][2], acc[i][3]);
        *(float4*)&g_nh[off] = v;
    }
}

// ---------------------------------------------------------------------------
// Kernel 2: per-edge gate  coeff[e] = edge_fts[e,:] . W_e + b_e
// one warp per edge, coalesced 2x128B loads, shfl reduce.
// ---------------------------------------------------------------------------
__global__ __launch_bounds__(256)
void k_coeff(const float* __restrict__ ef,
             const float* __restrict__ We,
             const float* __restrict__ be)
{
    int w    = (blockIdx.x * blockDim.x + threadIdx.x) >> 5;
    int lane = threadIdx.x & 31;
    if (w >= EDGES) return;

    const float* row = ef + (size_t)w * 64;
    float s = row[lane]      * __ldg(&We[lane])
            + row[lane + 32] * __ldg(&We[lane + 32]);

    #pragma unroll
    for (int off = 16; off > 0; off >>= 1)
        s += __shfl_xor_sync(0xFFFFFFFFu, s, off);

    if (lane == 0) g_coeff[w] = s + __ldg(&be[0]);
}

// ---------------------------------------------------------------------------
// Kernel 3: gather-by-src, scale, scatter-sum-by-tgt.
// one warp per edge; 256 floats per edge = 2 float4 per lane.
// vectorized no-return atomics: red.global.add.v4.f32 (sm_90+).
// edge_indices handed over as int32 pairs (JAX x64-disabled downcast).
// ---------------------------------------------------------------------------
__global__ __launch_bounds__(256)
void k_scatter(const int* __restrict__ idx,
               float* __restrict__ out)
{
    int w    = (blockIdx.x * blockDim.x + threadIdx.x) >> 5;
    int lane = threadIdx.x & 31;
    if (w >= EDGES) return;

    int b = w / Ee;                                   // batch index
    int src = idx[(size_t)w * 2 + 0];
    int tgt = idx[(size_t)w * 2 + 1];
    float cf = g_coeff[w];

    const float4* s4 = (const float4*)(g_nh + ((size_t)b * Nn + (size_t)src) * 256);
    float*        t  = out + ((size_t)b * Nn + (size_t)tgt) * 256;

    #pragma unroll
    for (int k = 0; k < 2; k++) {
        int i = k * 32 + lane;                        // float4 index 0..63
        float4 v = __ldg(&s4[i]);
        float rx = v.x * cf, ry = v.y * cf, rz = v.z * cf, rw = v.w * cf;
        asm volatile("red.global.add.v4.f32 [%0], {%1, %2, %3, %4};"
                     :: "l"(t + (size_t)i * 4), "f"(rx), "f"(ry), "f"(rz), "f"(rw)
                     : "memory");
    }
}

// ---------------------------------------------------------------------------
// launch: project -> coeff -> memset(out) -> scatter   (single default stream)
// inputs (metadata order): node_fts, hidden, edge_fts, W_nh, b_nh, W_e, b_e,
//                          edge_indices(int32 pairs)
// ---------------------------------------------------------------------------
extern "C" void kernel_launch(void* const* d_in, const int* in_sizes, int n_in,
                              void* d_out, int out_size)
{
    const float* node   = (const float*)d_in[0];
    const float* hidden = (const float*)d_in[1];
    const float* ef     = (const float*)d_in[2];
    const float* Wnh    = (const float*)d_in[3];
    const float* bnh    = (const float*)d_in[4];
    const float* We     = (const float*)d_in[5];
    const float* be     = (const float*)d_in[6];
    const int*   idx    = (const int*)d_in[7];
    float*       out    = (float*)d_out;

    cudaFuncSetAttribute(k_project, cudaFuncAttributeMaxDynamicSharedMemorySize,
                         PROJ_SMEM_BYTES);

    // 1) projection: 160000 rows / 64 per block
    k_project<<<ROWS / PROJ_ROWS_PER_BLK, 256, PROJ_SMEM_BYTES>>>(node, hidden, Wnh, bnh);

    // 2) per-edge gate: 640000 warps, 8 per block
    k_coeff<<<(EDGES + 7) / 8, 256>>>(ef, We, be);

    // 3) zero output (poisoned by harness), then scatter
    cudaMemsetAsync(d_out, 0, (size_t)out_size * sizeof(float), 0);
    k_scatter<<<(EDGES + 7) / 8, 256>>>(idx, out);
}